// round 8
// baseline (speedup 1.0000x reference)
#include <cuda_runtime.h>
#include <cuda_bf16.h>
#include <math.h>

#define HD   20
#define TPB  96
#define CH_W 16
#define XB   96

typedef unsigned long long ull;

__device__ __forceinline__ float tanh_fast(float x) {
    float y; asm("tanh.approx.f32 %0, %1;" : "=f"(y) : "f"(x)); return y;
}
__device__ __forceinline__ ull pack2(float a, float b) {
    ull r; asm("mov.b64 %0, {%1,%2};" : "=l"(r) : "f"(a), "f"(b)); return r;
}
__device__ __forceinline__ float2 unpack2(ull p) {
    float2 v; asm("mov.b64 {%0,%1}, %2;" : "=f"(v.x), "=f"(v.y) : "l"(p)); return v;
}
__device__ __forceinline__ ull ffma2(ull a, ull b, ull c) {
    ull r; asm("fma.rn.f32x2 %0, %1, %2, %3;" : "=l"(r) : "l"(a), "l"(b), "l"(c)); return r;
}
__device__ __forceinline__ ull add2(ull a, ull b) {
    ull r; asm("add.rn.f32x2 %0, %1, %2;" : "=l"(r) : "l"(a), "l"(b)); return r;
}

// Gate activations + cell update; state advances only when `on`.
__device__ __forceinline__ void lstm_act(ull A0, ull A1, ull B0, ull B1,
                                         bool on, float& cst, float& h) {
    float2 pif = unpack2(add2(A0, A1));   // (pre_i, pre_f)
    float2 pgo = unpack2(add2(B0, B1));   // (pre_g, pre_o)
    float gi = fmaf(tanh_fast(0.5f * pif.x), 0.5f, 0.5f);
    float gf = fmaf(tanh_fast(0.5f * pif.y), 0.5f, 0.5f);
    float gg = tanh_fast(pgo.x);
    float go = fmaf(tanh_fast(0.5f * pgo.y), 0.5f, 0.5f);
    float nc = fmaf(gf, cst, gi * gg);
    float nh = go * tanh_fast(nc);
    if (on) { cst = nc; h = nh; }
}

// 96 threads/block, 3-warp pipeline, TWO independent chunks per block (ILP).
//   w0: layer-1 LSTM @ t for both chunks        -> hd0[c][i&1]
//   w2: proj[t-1] = Wih1^T y0 + b (both chunks) -> pr[c][(i-1)&1]; also the
//       linear head for t-3 (reads hd1[c][(i-1)&1]) + output store
//   w1: layer-2 LSTM @ t-2 for both chunks      -> hd1[c][i&1]
// Lane u owns unit u; gate pairs packed f32x2: A=(i,f), B=(g,o).
// h stored as duplicated pairs (h,h); weights SHARED between the two chunks.
__global__ __launch_bounds__(TPB, 4)
void lstm_opt_kernel(const float* __restrict__ grad,
                     const float* __restrict__ Wih0, const float* __restrict__ Whh0,
                     const float* __restrict__ bih0, const float* __restrict__ bhh0,
                     const float* __restrict__ Wih1, const float* __restrict__ Whh1,
                     const float* __restrict__ bih1, const float* __restrict__ bhh1,
                     const float* __restrict__ Wlin, const float* __restrict__ blin,
                     float* __restrict__ out, int N, int out_size, int chl)
{
    __shared__ __align__(16) float2 xbuf[2][XB];
    __shared__ __align__(16) ull hd0[2][2][32];        // [chunk][phase][lane]
    __shared__ __align__(16) ull hd1[2][2][32];
    __shared__ __align__(16) ulonglong2 pr[2][2][32];  // proj {A=(i,f), B=(g,o)}

    const int tid  = threadIdx.x;
    const int wid  = tid >> 5;
    const int lane = tid & 31;
    const int u    = lane;
    const bool act = (u < HD);

    // ---- per-warp weight set (registers, shared across both chunks) ----
    ull wA[20], wB[20];
    ull biasA = 0ull, biasB = 0ull;
    ull wxA0 = 0ull, wxA1 = 0ull, wxB0 = 0ull, wxB1 = 0ull;
    float wlin_u = 0.f;
    #pragma unroll
    for (int k = 0; k < 20; k++) { wA[k] = 0ull; wB[k] = 0ull; }

    if (act) {
        if (wid == 0) {            // L1 recurrence
            #pragma unroll
            for (int k = 0; k < 20; k++) {
                wA[k] = pack2(Whh0[u * HD + k],            Whh0[(HD + u) * HD + k]);
                wB[k] = pack2(Whh0[(2 * HD + u) * HD + k], Whh0[(3 * HD + u) * HD + k]);
            }
            wxA0 = pack2(Wih0[u * 2 + 0],            Wih0[(HD + u) * 2 + 0]);
            wxA1 = pack2(Wih0[u * 2 + 1],            Wih0[(HD + u) * 2 + 1]);
            wxB0 = pack2(Wih0[(2 * HD + u) * 2 + 0], Wih0[(3 * HD + u) * 2 + 0]);
            wxB1 = pack2(Wih0[(2 * HD + u) * 2 + 1], Wih0[(3 * HD + u) * 2 + 1]);
            biasA = pack2(bih0[u] + bhh0[u],                   bih0[HD + u] + bhh0[HD + u]);
            biasB = pack2(bih0[2 * HD + u] + bhh0[2 * HD + u], bih0[3 * HD + u] + bhh0[3 * HD + u]);
        } else if (wid == 1) {     // L2 recurrence
            #pragma unroll
            for (int k = 0; k < 20; k++) {
                wA[k] = pack2(Whh1[u * HD + k],            Whh1[(HD + u) * HD + k]);
                wB[k] = pack2(Whh1[(2 * HD + u) * HD + k], Whh1[(3 * HD + u) * HD + k]);
            }
        } else {                   // y0 -> L2 projection (+ bias) and linear head
            #pragma unroll
            for (int k = 0; k < 20; k++) {
                wA[k] = pack2(Wih1[u * HD + k],            Wih1[(HD + u) * HD + k]);
                wB[k] = pack2(Wih1[(2 * HD + u) * HD + k], Wih1[(3 * HD + u) * HD + k]);
            }
            biasA = pack2(bih1[u] + bhh1[u],                   bih1[HD + u] + bhh1[HD + u]);
            biasB = pack2(bih1[2 * HD + u] + bhh1[2 * HD + u], bih1[3 * HD + u] + bhh1[3 * HD + u]);
            wlin_u = Wlin[u];
        }
    }
    const float blinsc = blin[0] * 0.01f;

    // ---- two chunks per block ----
    const int start0 = blockIdx.x * 2 * chl;
    if (start0 >= N) return;
    const int end0  = min(N, start0 + chl);
    const int s20   = max(0, start0 - CH_W);
    const int s10   = max(0, s20 - CH_W);
    const int span0 = end0 - s10;
    const int i2lo0 = s20 - s10 + 1;
    const int ihlo0 = start0 - s10 + 3;

    const int start1 = start0 + chl;
    const bool live1 = (start1 < N);
    const int end1   = live1 ? min(N, start1 + chl) : 0;
    const int s21    = live1 ? max(0, start1 - CH_W) : 0;
    const int s11    = live1 ? max(0, s21 - CH_W) : 0;
    const int span1  = live1 ? (end1 - s11) : -5;
    const int i2lo1  = live1 ? (s21 - s11 + 1) : (1 << 28);
    const int ihlo1  = live1 ? (start1 - s11 + 3) : (1 << 28);

    // ---- preprocess grad -> (log, sign) features for both chunks ----
    for (int i = tid; i < XB; i += TPB) {
        float g0  = grad[min(s10 + i, N - 1)];
        float lg0 = fminf(1.f, fmaxf(-1.f, __logf(fabsf(g0) + 1e-8f) * 0.1f));
        float sg0 = fminf(1.f, fmaxf(-1.f, g0 * 22026.4657948067f));
        xbuf[0][i] = make_float2(lg0, sg0);
        float g1  = grad[min(s11 + i, N - 1)];
        float lg1 = fminf(1.f, fmaxf(-1.f, __logf(fabsf(g1) + 1e-8f) * 0.1f));
        float sg1 = fminf(1.f, fmaxf(-1.f, g1 * 22026.4657948067f));
        xbuf[1][i] = make_float2(lg1, sg1);
    }
    for (int i = tid; i < 128; i += TPB) {
        ((ull*)hd0)[i] = 0ull;
        ((ull*)hd1)[i] = 0ull;
        ((ulonglong2*)pr)[i] = make_ulonglong2(0ull, 0ull);
    }
    __syncthreads();

    float csA = 0.f, hA = 0.f, csB = 0.f, hB = 0.f;   // chunk0 / chunk1 states
    float2 xv0 = xbuf[0][0], xv1 = xbuf[1][0];
    const int nIter = max(span0, span1) + 3;

    for (int i = 0; i < nIter; ++i) {
        const int p = i & 1;

        if (wid == 0) {
            // ---- L1 @ t for both chunks, fused for ILP ----
            const bool on0 = (i < span0), on1 = (i < span1);
            ull xx0 = pack2(xv0.x, xv0.x), xy0 = pack2(xv0.y, xv0.y);
            ull xx1 = pack2(xv1.x, xv1.x), xy1 = pack2(xv1.y, xv1.y);
            ull aA00 = ffma2(wxA0, xx0, ffma2(wxA1, xy0, biasA));
            ull aB00 = ffma2(wxB0, xx0, ffma2(wxB1, xy0, biasB));
            ull aA01 = ffma2(wxA0, xx1, ffma2(wxA1, xy1, biasA));
            ull aB01 = ffma2(wxB0, xx1, ffma2(wxB1, xy1, biasB));
            ull aA10 = 0ull, aB10 = 0ull, aA11 = 0ull, aB11 = 0ull;
            const ulonglong2* b0 = (const ulonglong2*)hd0[0][p ^ 1];
            const ulonglong2* b1 = (const ulonglong2*)hd0[1][p ^ 1];
            #pragma unroll
            for (int j = 0; j < 10; j++) {
                ulonglong2 t0 = b0[j], t1 = b1[j];
                aA00 = ffma2(wA[2*j], t0.x, aA00); aA10 = ffma2(wA[2*j+1], t0.y, aA10);
                aB00 = ffma2(wB[2*j], t0.x, aB00); aB10 = ffma2(wB[2*j+1], t0.y, aB10);
                aA01 = ffma2(wA[2*j], t1.x, aA01); aA11 = ffma2(wA[2*j+1], t1.y, aA11);
                aB01 = ffma2(wB[2*j], t1.x, aB01); aB11 = ffma2(wB[2*j+1], t1.y, aB11);
            }
            lstm_act(aA00, aA10, aB00, aB10, on0, csA, hA);
            if (on0) hd0[0][p][u] = pack2(hA, hA);
            lstm_act(aA01, aA11, aB01, aB11, on1, csB, hB);
            if (on1) hd0[1][p][u] = pack2(hB, hB);
            xv0 = xbuf[0][i + 1];
            xv1 = xbuf[1][i + 1];
        } else if (wid == 1) {
            // ---- L2 @ t-2 for both chunks ----
            const bool on0 = (i >= i2lo0 + 1) && (i <= span0 + 1);
            const bool on1 = (i >= i2lo1 + 1) && (i <= span1 + 1);
            ulonglong2 pv0 = pr[0][p][u], pv1 = pr[1][p][u];
            ull aA00 = pv0.x, aB00 = pv0.y, aA01 = pv1.x, aB01 = pv1.y;
            ull aA10 = 0ull, aB10 = 0ull, aA11 = 0ull, aB11 = 0ull;
            const ulonglong2* b0 = (const ulonglong2*)hd1[0][p ^ 1];
            const ulonglong2* b1 = (const ulonglong2*)hd1[1][p ^ 1];
            #pragma unroll
            for (int j = 0; j < 10; j++) {
                ulonglong2 t0 = b0[j], t1 = b1[j];
                aA00 = ffma2(wA[2*j], t0.x, aA00); aA10 = ffma2(wA[2*j+1], t0.y, aA10);
                aB00 = ffma2(wB[2*j], t0.x, aB00); aB10 = ffma2(wB[2*j+1], t0.y, aB10);
                aA01 = ffma2(wA[2*j], t1.x, aA01); aA11 = ffma2(wA[2*j+1], t1.y, aA11);
                aB01 = ffma2(wB[2*j], t1.x, aB01); aB11 = ffma2(wB[2*j+1], t1.y, aB11);
            }
            lstm_act(aA00, aA10, aB00, aB10, on0, csA, hA);
            if (on0) hd1[0][p][u] = pack2(hA, hA);
            lstm_act(aA01, aA11, aB01, aB11, on1, csB, hB);
            if (on1) hd1[1][p][u] = pack2(hB, hB);
        } else {
            // ---- linear head @ t-3 (reads hd1 written last iter) ----
            if (i >= ihlo0 && i <= span0 + 2) {
                float hv = ((const float*)&hd1[0][p ^ 1][u])[0];
                float part = hv * wlin_u;
                part += __shfl_xor_sync(0xFFFFFFFFu, part, 16);
                part += __shfl_xor_sync(0xFFFFFFFFu, part, 8);
                part += __shfl_xor_sync(0xFFFFFFFFu, part, 4);
                part += __shfl_xor_sync(0xFFFFFFFFu, part, 2);
                part += __shfl_xor_sync(0xFFFFFFFFu, part, 1);
                if (lane == 0) out[s10 + i - 3] = fmaf(part, 0.01f, blinsc);
            }
            if (i >= ihlo1 && i <= span1 + 2) {
                float hv = ((const float*)&hd1[1][p ^ 1][u])[0];
                float part = hv * wlin_u;
                part += __shfl_xor_sync(0xFFFFFFFFu, part, 16);
                part += __shfl_xor_sync(0xFFFFFFFFu, part, 8);
                part += __shfl_xor_sync(0xFFFFFFFFu, part, 4);
                part += __shfl_xor_sync(0xFFFFFFFFu, part, 2);
                part += __shfl_xor_sync(0xFFFFFFFFu, part, 1);
                if (lane == 0) out[s11 + i - 3] = fmaf(part, 0.01f, blinsc);
            }
            // ---- proj @ t-1 for both chunks (store guarded) ----
            ull aA00 = biasA, aB00 = biasB, aA01 = biasA, aB01 = biasB;
            ull aA10 = 0ull, aB10 = 0ull, aA11 = 0ull, aB11 = 0ull;
            const ulonglong2* b0 = (const ulonglong2*)hd0[0][p ^ 1];
            const ulonglong2* b1 = (const ulonglong2*)hd0[1][p ^ 1];
            #pragma unroll
            for (int j = 0; j < 10; j++) {
                ulonglong2 t0 = b0[j], t1 = b1[j];
                aA00 = ffma2(wA[2*j], t0.x, aA00); aA10 = ffma2(wA[2*j+1], t0.y, aA10);
                aB00 = ffma2(wB[2*j], t0.x, aB00); aB10 = ffma2(wB[2*j+1], t0.y, aB10);
                aA01 = ffma2(wA[2*j], t1.x, aA01); aA11 = ffma2(wA[2*j+1], t1.y, aA11);
                aB01 = ffma2(wB[2*j], t1.x, aB01); aB11 = ffma2(wB[2*j+1], t1.y, aB11);
            }
            if (i >= i2lo0 && i <= span0)
                pr[0][p ^ 1][u] = make_ulonglong2(add2(aA00, aA10), add2(aB00, aB10));
            if (i >= i2lo1 && i <= span1)
                pr[1][p ^ 1][u] = make_ulonglong2(add2(aA01, aA11), add2(aB01, aB11));
        }
        __syncthreads();
    }

    // final states: [update(N), h0(20), h1(20), c0(20), c1(20)]
    if (out_size >= N + 80 && act) {
        if (wid == 0) {
            if (end0 == N)          { out[N + u]      = hA; out[N + 40 + u] = csA; }
            if (live1 && end1 == N) { out[N + u]      = hB; out[N + 40 + u] = csB; }
        } else if (wid == 1) {
            if (end0 == N)          { out[N + 20 + u] = hA; out[N + 60 + u] = csA; }
            if (live1 && end1 == N) { out[N + 20 + u] = hB; out[N + 60 + u] = csB; }
        }
    }
}

extern "C" void kernel_launch(void* const* d_in, const int* in_sizes, int n_in,
                              void* d_out, int out_size) {
    const float* grad = (const float*)d_in[0];
    const float* Wih0 = (const float*)d_in[1];
    const float* Whh0 = (const float*)d_in[2];
    const float* bih0 = (const float*)d_in[3];
    const float* bhh0 = (const float*)d_in[4];
    const float* Wih1 = (const float*)d_in[5];
    const float* Whh1 = (const float*)d_in[6];
    const float* bih1 = (const float*)d_in[7];
    const float* bhh1 = (const float*)d_in[8];
    const float* Wlin = (const float*)d_in[9];
    const float* blin = (const float*)d_in[10];

    int N = in_sizes[0];
    // 1184 chunk slots = 4 blocks/SM x 148 SMs x 2 chunks/block, one wave
    int chl = (N + 1183) / 1184;
    if (chl > XB - 2 * CH_W - 4) chl = XB - 2 * CH_W - 4;
    if (chl < 1) chl = 1;
    int grid = (N + 2 * chl - 1) / (2 * chl);
    lstm_opt_kernel<<<grid, TPB>>>(grad, Wih0, Whh0, bih0, bhh0,
                                   Wih1, Whh1, bih1, bhh1, Wlin, blin,
                                   (float*)d_out, N, out_size, chl);
}

// round 9
// speedup vs baseline: 1.0920x; 1.0920x over previous
#include <cuda_runtime.h>
#include <cuda_bf16.h>
#include <math.h>

#define HD   20
#define TPB  96
#define CH_W 16
#define XB   128
#define KW   8          // steps per barrier window
#define RING 16         // 2*KW slots

typedef unsigned long long ull;

__device__ __forceinline__ float tanh_fast(float x) {
    float y; asm("tanh.approx.f32 %0, %1;" : "=f"(y) : "f"(x)); return y;
}
__device__ __forceinline__ ull pack2(float a, float b) {
    ull r; asm("mov.b64 %0, {%1,%2};" : "=l"(r) : "f"(a), "f"(b)); return r;
}
__device__ __forceinline__ float2 unpack2(ull p) {
    float2 v; asm("mov.b64 {%0,%1}, %2;" : "=f"(v.x), "=f"(v.y) : "l"(p)); return v;
}
__device__ __forceinline__ ull ffma2(ull a, ull b, ull c) {
    ull r; asm("fma.rn.f32x2 %0, %1, %2, %3;" : "=l"(r) : "l"(a), "l"(b), "l"(c)); return r;
}
__device__ __forceinline__ ull add2(ull a, ull b) {
    ull r; asm("add.rn.f32x2 %0, %1, %2;" : "=l"(r) : "l"(a), "l"(b)); return r;
}

// Gate activations + cell update (A=(i,f), B=(g,o) packed pre-activations).
__device__ __forceinline__ void lstm_act(ull A0, ull A1, ull B0, ull B1,
                                         float& cst, float& h) {
    float2 pif = unpack2(add2(A0, A1));
    float2 pgo = unpack2(add2(B0, B1));
    float gi = fmaf(tanh_fast(0.5f * pif.x), 0.5f, 0.5f);
    float gf = fmaf(tanh_fast(0.5f * pif.y), 0.5f, 0.5f);
    float gg = tanh_fast(pgo.x);
    float go = fmaf(tanh_fast(0.5f * pgo.y), 0.5f, 0.5f);
    cst = fmaf(gf, cst, gi * gg);
    h   = go * tanh_fast(cst);
}

// 96 threads/block; 3-warp WINDOW pipeline, one __syncthreads per KW=8 steps.
//   w0: L1 LSTM, steps [w*K,(w+1)*K)   -> hd0ring[t & 15]
//   w2: proj = Wih1^T y0 + b, lag K    -> pr[t & 15]      (reads hd0ring)
//   w1: L2 LSTM + linear head, lag 2K  (reads pr, own hd1 ping-pong)
// Lane u owns unit u; gate pairs packed f32x2. h stored as dup pairs (h,h).
// Intra-warp cross-lane h exchange: STS -> __syncwarp -> LDS (warp-local).
__global__ __launch_bounds__(TPB, 5)
void lstm_opt_kernel(const float* __restrict__ grad,
                     const float* __restrict__ Wih0, const float* __restrict__ Whh0,
                     const float* __restrict__ bih0, const float* __restrict__ bhh0,
                     const float* __restrict__ Wih1, const float* __restrict__ Whh1,
                     const float* __restrict__ bih1, const float* __restrict__ bhh1,
                     const float* __restrict__ Wlin, const float* __restrict__ blin,
                     float* __restrict__ out, int N, int out_size, int chl)
{
    __shared__ __align__(16) float2 xbuf[XB];
    __shared__ __align__(16) ull hd0ring[RING][32];
    __shared__ __align__(16) ulonglong2 pr[RING][32];
    __shared__ __align__(16) ull hd1[2][32];

    const int tid  = threadIdx.x;
    const int wid  = tid >> 5;
    const int lane = tid & 31;
    const int u    = lane;
    const bool act = (u < HD);

    // ---- per-warp weight set in registers ----
    ull wA[20], wB[20];
    ull biasA = 0ull, biasB = 0ull;
    ull wxA0 = 0ull, wxA1 = 0ull, wxB0 = 0ull, wxB1 = 0ull;
    float wlin_u = 0.f;
    #pragma unroll
    for (int k = 0; k < 20; k++) { wA[k] = 0ull; wB[k] = 0ull; }

    if (act) {
        if (wid == 0) {            // L1 recurrence
            #pragma unroll
            for (int k = 0; k < 20; k++) {
                wA[k] = pack2(Whh0[u * HD + k],            Whh0[(HD + u) * HD + k]);
                wB[k] = pack2(Whh0[(2 * HD + u) * HD + k], Whh0[(3 * HD + u) * HD + k]);
            }
            wxA0 = pack2(Wih0[u * 2 + 0],            Wih0[(HD + u) * 2 + 0]);
            wxA1 = pack2(Wih0[u * 2 + 1],            Wih0[(HD + u) * 2 + 1]);
            wxB0 = pack2(Wih0[(2 * HD + u) * 2 + 0], Wih0[(3 * HD + u) * 2 + 0]);
            wxB1 = pack2(Wih0[(2 * HD + u) * 2 + 1], Wih0[(3 * HD + u) * 2 + 1]);
            biasA = pack2(bih0[u] + bhh0[u],                   bih0[HD + u] + bhh0[HD + u]);
            biasB = pack2(bih0[2 * HD + u] + bhh0[2 * HD + u], bih0[3 * HD + u] + bhh0[3 * HD + u]);
        } else if (wid == 1) {     // L2 recurrence + head
            #pragma unroll
            for (int k = 0; k < 20; k++) {
                wA[k] = pack2(Whh1[u * HD + k],            Whh1[(HD + u) * HD + k]);
                wB[k] = pack2(Whh1[(2 * HD + u) * HD + k], Whh1[(3 * HD + u) * HD + k]);
            }
            wlin_u = Wlin[u];
        } else {                   // y0 -> L2 projection (+ L2 bias)
            #pragma unroll
            for (int k = 0; k < 20; k++) {
                wA[k] = pack2(Wih1[u * HD + k],            Wih1[(HD + u) * HD + k]);
                wB[k] = pack2(Wih1[(2 * HD + u) * HD + k], Wih1[(3 * HD + u) * HD + k]);
            }
            biasA = pack2(bih1[u] + bhh1[u],                   bih1[HD + u] + bhh1[HD + u]);
            biasB = pack2(bih1[2 * HD + u] + bhh1[2 * HD + u], bih1[3 * HD + u] + bhh1[3 * HD + u]);
        }
    }
    const float blinsc = blin[0] * 0.01f;

    // ---- chunk ranges ----
    const int start_out = blockIdx.x * chl;
    if (start_out >= N) return;
    const int end_out = min(N, start_out + chl);
    const int s2      = max(0, start_out - CH_W);
    const int s1      = max(0, s2 - CH_W);
    const int span    = end_out - s1;
    const int i2      = s2 - s1;           // first L2-active step index
    const int ihl     = start_out - s1;    // first head-output step index

    // ---- preprocess + zero-init ----
    for (int i = tid; i < span; i += TPB) {
        float g  = grad[s1 + i];
        float lg = fminf(1.f, fmaxf(-1.f, __logf(fabsf(g) + 1e-8f) * 0.1f));
        float sg = fminf(1.f, fmaxf(-1.f, g * 22026.4657948067f));   // exp(10)
        xbuf[i] = make_float2(lg, sg);
    }
    for (int i = tid; i < RING * 32; i += TPB) {
        ((ull*)hd0ring)[i] = 0ull;
        ((ulonglong2*)pr)[i] = make_ulonglong2(0ull, 0ull);
    }
    if (tid < 64) ((ull*)hd1)[tid] = 0ull;
    __syncthreads();

    float cst = 0.f, h = 0.f;
    const int NW = (span + KW - 1) / KW + 2;

    for (int w = 0; w < NW; ++w) {
        if (wid == 0) {
            // ---- L1: steps [w*KW, w*KW+KW) ----
            #pragma unroll
            for (int k = 0; k < KW; ++k) {
                const int t = w * KW + k;
                if (t < span) {
                    float2 xv = xbuf[t];
                    ull xx = pack2(xv.x, xv.x), xy = pack2(xv.y, xv.y);
                    ull aA0 = ffma2(wxA0, xx, ffma2(wxA1, xy, biasA));
                    ull aB0 = ffma2(wxB0, xx, ffma2(wxB1, xy, biasB));
                    ull aA1 = 0ull, aB1 = 0ull;
                    const ulonglong2* hb = (const ulonglong2*)hd0ring[(t + RING - 1) & (RING - 1)];
                    #pragma unroll
                    for (int j = 0; j < 10; j++) {
                        ulonglong2 tv = hb[j];
                        aA0 = ffma2(wA[2*j], tv.x, aA0); aA1 = ffma2(wA[2*j+1], tv.y, aA1);
                        aB0 = ffma2(wB[2*j], tv.x, aB0); aB1 = ffma2(wB[2*j+1], tv.y, aB1);
                    }
                    lstm_act(aA0, aA1, aB0, aB1, cst, h);
                    hd0ring[t & (RING - 1)][u] = pack2(h, h);
                }
                __syncwarp();
            }
        } else if (wid == 2) {
            // ---- proj: steps [(w-1)*KW, (w-1)*KW+KW) ----
            #pragma unroll
            for (int k = 0; k < KW; ++k) {
                const int tp = (w - 1) * KW + k;
                if (tp >= i2 && tp < span) {
                    ull aA0 = biasA, aA1 = 0ull, aB0 = biasB, aB1 = 0ull;
                    const ulonglong2* yb = (const ulonglong2*)hd0ring[tp & (RING - 1)];
                    #pragma unroll
                    for (int j = 0; j < 10; j++) {
                        ulonglong2 tv = yb[j];
                        aA0 = ffma2(wA[2*j], tv.x, aA0); aA1 = ffma2(wA[2*j+1], tv.y, aA1);
                        aB0 = ffma2(wB[2*j], tv.x, aB0); aB1 = ffma2(wB[2*j+1], tv.y, aB1);
                    }
                    pr[tp & (RING - 1)][u] =
                        make_ulonglong2(add2(aA0, aA1), add2(aB0, aB1));
                }
            }
        } else {
            // ---- L2 + head: steps [(w-2)*KW, (w-2)*KW+KW) ----
            #pragma unroll
            for (int k = 0; k < KW; ++k) {
                const int t1 = (w - 2) * KW + k;
                if (t1 >= i2 && t1 < span) {
                    const int pp = t1 & 1;
                    ulonglong2 pv = pr[t1 & (RING - 1)][u];
                    ull aA0 = pv.x, aB0 = pv.y, aA1 = 0ull, aB1 = 0ull;
                    const ulonglong2* hb = (const ulonglong2*)hd1[pp ^ 1];
                    #pragma unroll
                    for (int j = 0; j < 10; j++) {
                        ulonglong2 tv = hb[j];
                        aA0 = ffma2(wA[2*j], tv.x, aA0); aA1 = ffma2(wA[2*j+1], tv.y, aA1);
                        aB0 = ffma2(wB[2*j], tv.x, aB0); aB1 = ffma2(wB[2*j+1], tv.y, aB1);
                    }
                    lstm_act(aA0, aA1, aB0, aB1, cst, h);
                    hd1[pp][u] = pack2(h, h);
                    if (t1 >= ihl) {
                        float part = h * wlin_u;           // zero on idle lanes
                        part += __shfl_xor_sync(0xFFFFFFFFu, part, 16);
                        part += __shfl_xor_sync(0xFFFFFFFFu, part, 8);
                        part += __shfl_xor_sync(0xFFFFFFFFu, part, 4);
                        part += __shfl_xor_sync(0xFFFFFFFFu, part, 2);
                        part += __shfl_xor_sync(0xFFFFFFFFu, part, 1);
                        if (lane == 0) out[s1 + t1] = fmaf(part, 0.01f, blinsc);
                    }
                }
                __syncwarp();
            }
        }
        __syncthreads();
    }

    // final states: [update(N), h0(20), h1(20), c0(20), c1(20)]
    if (end_out == N && out_size >= N + 80 && act) {
        if (wid == 0)      { out[N + u]      = h; out[N + 40 + u] = cst; }
        else if (wid == 1) { out[N + 20 + u] = h; out[N + 60 + u] = cst; }
    }
}

extern "C" void kernel_launch(void* const* d_in, const int* in_sizes, int n_in,
                              void* d_out, int out_size) {
    const float* grad = (const float*)d_in[0];
    const float* Wih0 = (const float*)d_in[1];
    const float* Whh0 = (const float*)d_in[2];
    const float* bih0 = (const float*)d_in[3];
    const float* bhh0 = (const float*)d_in[4];
    const float* Wih1 = (const float*)d_in[5];
    const float* Whh1 = (const float*)d_in[6];
    const float* bih1 = (const float*)d_in[7];
    const float* bhh1 = (const float*)d_in[8];
    const float* Wlin = (const float*)d_in[9];
    const float* blin = (const float*)d_in[10];

    int N = in_sizes[0];
    // 740 chunk slots = 5 blocks/SM x 148 SMs, one wave
    int chl = (N + 739) / 740;
    if (chl > XB - 2 * CH_W) chl = XB - 2 * CH_W;
    if (chl < 1) chl = 1;
    int grid = (N + chl - 1) / chl;
    lstm_opt_kernel<<<grid, TPB>>>(grad, Wih0, Whh0, bih0, bhh0,
                                   Wih1, Whh1, bih1, bhh1, Wlin, blin,
                                   (float*)d_out, N, out_size, chl);
}

// round 10
// speedup vs baseline: 1.1379x; 1.0420x over previous
#include <cuda_runtime.h>
#include <cuda_bf16.h>
#include <math.h>

#define HD   20
#define TPB  96
#define CH_W 16
#define XB   128
#define KW   8          // steps per barrier window
#define RING 16         // 2*KW slots

typedef unsigned long long ull;

__device__ __forceinline__ float tanh_fast(float x) {
    float y; asm("tanh.approx.f32 %0, %1;" : "=f"(y) : "f"(x)); return y;
}
__device__ __forceinline__ ull pack2(float a, float b) {
    ull r; asm("mov.b64 %0, {%1,%2};" : "=l"(r) : "f"(a), "f"(b)); return r;
}
__device__ __forceinline__ float2 unpack2(ull p) {
    float2 v; asm("mov.b64 {%0,%1}, %2;" : "=f"(v.x), "=f"(v.y) : "l"(p)); return v;
}
__device__ __forceinline__ ull ffma2(ull a, ull b, ull c) {
    ull r; asm("fma.rn.f32x2 %0, %1, %2, %3;" : "=l"(r) : "l"(a), "l"(b), "l"(c)); return r;
}
__device__ __forceinline__ float hsum(ull p) {
    float2 v = unpack2(p); return v.x + v.y;
}

// 4-gate activation + cell update from per-gate packed accumulators.
__device__ __forceinline__ void lstm_act4(ull aI, ull aF, ull aG, ull aO,
                                          float& cst, float& h) {
    float pi = hsum(aI), pf = hsum(aF), pg = hsum(aG), po = hsum(aO);
    float gi = fmaf(tanh_fast(0.5f * pi), 0.5f, 0.5f);
    float gf = fmaf(tanh_fast(0.5f * pf), 0.5f, 0.5f);
    float gg = tanh_fast(pg);
    float go = fmaf(tanh_fast(0.5f * po), 0.5f, 0.5f);
    cst = fmaf(gf, cst, gi * gg);
    h   = go * tanh_fast(cst);
}

// 20-dim dot for all 4 gates: h as raw float4 pairs, weights k-pair packed.
#define DOT20(WI, WF, WG, WO, HB, aI, aF, aG, aO) do {                        \
    _Pragma("unroll")                                                         \
    for (int j = 0; j < 5; j++) {                                             \
        ulonglong2 hp = (HB)[j];   /* (h4j,h4j+1) , (h4j+2,h4j+3) */          \
        aI = ffma2((WI)[2*j], hp.x, aI); aI = ffma2((WI)[2*j+1], hp.y, aI);   \
        aF = ffma2((WF)[2*j], hp.x, aF); aF = ffma2((WF)[2*j+1], hp.y, aF);   \
        aG = ffma2((WG)[2*j], hp.x, aG); aG = ffma2((WG)[2*j+1], hp.y, aG);   \
        aO = ffma2((WO)[2*j], hp.x, aO); aO = ffma2((WO)[2*j+1], hp.y, aO);   \
    }                                                                         \
} while (0)

// 96 threads/block; 3-warp WINDOW pipeline, one __syncthreads per KW=8 steps.
//   w0: L1 LSTM, steps [w*K,(w+1)*K)   -> h0ring[t & 15] (plain float)
//   w2: proj = Wih1^T y0 + b, lag K    -> pr[t & 15] (float4 pre-acts/lane)
//   w1: L2 LSTM + linear head, lag 2K  (reads pr, own h1 ping-pong)
// Lane u owns unit u. Weight regs: 4 gates x 10 ull = 80 regs/warp.
__global__ __launch_bounds__(TPB, 5)
void lstm_opt_kernel(const float* __restrict__ grad,
                     const float* __restrict__ Wih0, const float* __restrict__ Whh0,
                     const float* __restrict__ bih0, const float* __restrict__ bhh0,
                     const float* __restrict__ Wih1, const float* __restrict__ Whh1,
                     const float* __restrict__ bih1, const float* __restrict__ bhh1,
                     const float* __restrict__ Wlin, const float* __restrict__ blin,
                     float* __restrict__ out, int N, int out_size, int chl)
{
    __shared__ __align__(16) float2 xbuf[XB];
    __shared__ __align__(16) float h0ring[RING][32];
    __shared__ __align__(16) float4 pr[RING][32];
    __shared__ __align__(16) float h1buf[2][32];

    const int tid  = threadIdx.x;
    const int wid  = tid >> 5;
    const int lane = tid & 31;
    const int u    = lane;
    const bool act = (u < HD);

    // ---- per-warp weights: per-gate, k-pair packed ----
    ull wI[10], wF[10], wG[10], wO[10];
    ull bI = 0ull, bF = 0ull, bG = 0ull, bO = 0ull;   // packed (bias, 0) inits
    ull wxI = 0ull, wxF = 0ull, wxG = 0ull, wxO = 0ull;
    float wlin_u = 0.f;
    #pragma unroll
    for (int k = 0; k < 10; k++) { wI[k]=0ull; wF[k]=0ull; wG[k]=0ull; wO[k]=0ull; }

    if (act) {
        const float* Whh = (wid == 0) ? Whh0 : (wid == 1) ? Whh1 : Wih1;
        if (wid != 2) {
            #pragma unroll
            for (int k = 0; k < 10; k++) {
                wI[k] = pack2(Whh[u * HD + 2*k],            Whh[u * HD + 2*k + 1]);
                wF[k] = pack2(Whh[(HD + u) * HD + 2*k],     Whh[(HD + u) * HD + 2*k + 1]);
                wG[k] = pack2(Whh[(2 * HD + u) * HD + 2*k], Whh[(2 * HD + u) * HD + 2*k + 1]);
                wO[k] = pack2(Whh[(3 * HD + u) * HD + 2*k], Whh[(3 * HD + u) * HD + 2*k + 1]);
            }
        } else {
            #pragma unroll
            for (int k = 0; k < 10; k++) {
                wI[k] = pack2(Wih1[u * HD + 2*k],            Wih1[u * HD + 2*k + 1]);
                wF[k] = pack2(Wih1[(HD + u) * HD + 2*k],     Wih1[(HD + u) * HD + 2*k + 1]);
                wG[k] = pack2(Wih1[(2 * HD + u) * HD + 2*k], Wih1[(2 * HD + u) * HD + 2*k + 1]);
                wO[k] = pack2(Wih1[(3 * HD + u) * HD + 2*k], Wih1[(3 * HD + u) * HD + 2*k + 1]);
            }
        }
        if (wid == 0) {           // L1: x-projection + biases
            wxI = pack2(Wih0[u * 2 + 0],            Wih0[u * 2 + 1]);
            wxF = pack2(Wih0[(HD + u) * 2 + 0],     Wih0[(HD + u) * 2 + 1]);
            wxG = pack2(Wih0[(2 * HD + u) * 2 + 0], Wih0[(2 * HD + u) * 2 + 1]);
            wxO = pack2(Wih0[(3 * HD + u) * 2 + 0], Wih0[(3 * HD + u) * 2 + 1]);
            bI = pack2(bih0[u] + bhh0[u], 0.f);
            bF = pack2(bih0[HD + u] + bhh0[HD + u], 0.f);
            bG = pack2(bih0[2 * HD + u] + bhh0[2 * HD + u], 0.f);
            bO = pack2(bih0[3 * HD + u] + bhh0[3 * HD + u], 0.f);
        } else if (wid == 2) {    // proj: L2 biases folded here
            bI = pack2(bih1[u] + bhh1[u], 0.f);
            bF = pack2(bih1[HD + u] + bhh1[HD + u], 0.f);
            bG = pack2(bih1[2 * HD + u] + bhh1[2 * HD + u], 0.f);
            bO = pack2(bih1[3 * HD + u] + bhh1[3 * HD + u], 0.f);
        } else {
            wlin_u = Wlin[u];
        }
    }
    const float blinsc = blin[0] * 0.01f;

    // ---- chunk ranges ----
    const int start_out = blockIdx.x * chl;
    if (start_out >= N) return;
    const int end_out = min(N, start_out + chl);
    const int s2      = max(0, start_out - CH_W);
    const int s1      = max(0, s2 - CH_W);
    const int span    = end_out - s1;
    const int i2      = s2 - s1;           // first L2-active step index
    const int ihl     = start_out - s1;    // first head-output step index

    // ---- preprocess + zero-init ----
    for (int i = tid; i < span; i += TPB) {
        float g  = grad[s1 + i];
        float lg = fminf(1.f, fmaxf(-1.f, __logf(fabsf(g) + 1e-8f) * 0.1f));
        float sg = fminf(1.f, fmaxf(-1.f, g * 22026.4657948067f));   // exp(10)
        xbuf[i] = make_float2(lg, sg);
    }
    for (int i = tid; i < RING * 32; i += TPB) {
        ((float*)h0ring)[i] = 0.f;
        ((float4*)pr)[i] = make_float4(0.f, 0.f, 0.f, 0.f);
    }
    if (tid < 64) ((float*)h1buf)[tid] = 0.f;
    __syncthreads();

    float cst = 0.f, h = 0.f;
    const int NW = (span + KW - 1) / KW + 2;

    for (int w = 0; w < NW; ++w) {
        if (wid == 0) {
            // ---- L1: steps [w*KW, w*KW+KW) ----
            #pragma unroll
            for (int k = 0; k < KW; ++k) {
                const int t = w * KW + k;
                if (t < span) {
                    float2 xv = xbuf[t];
                    ull xp = pack2(xv.x, xv.y);
                    ull aI = ffma2(wxI, xp, bI);
                    ull aF = ffma2(wxF, xp, bF);
                    ull aG = ffma2(wxG, xp, bG);
                    ull aO = ffma2(wxO, xp, bO);
                    const ulonglong2* hb =
                        (const ulonglong2*)h0ring[(t + RING - 1) & (RING - 1)];
                    DOT20(wI, wF, wG, wO, hb, aI, aF, aG, aO);
                    lstm_act4(aI, aF, aG, aO, cst, h);
                    h0ring[t & (RING - 1)][u] = h;
                }
                __syncwarp();
            }
        } else if (wid == 2) {
            // ---- proj: steps [(w-1)*KW, (w-1)*KW+KW) ----
            #pragma unroll
            for (int k = 0; k < KW; ++k) {
                const int tp = (w - 1) * KW + k;
                if (tp >= i2 && tp < span) {
                    ull aI = bI, aF = bF, aG = bG, aO = bO;
                    const ulonglong2* yb =
                        (const ulonglong2*)h0ring[tp & (RING - 1)];
                    DOT20(wI, wF, wG, wO, yb, aI, aF, aG, aO);
                    pr[tp & (RING - 1)][u] =
                        make_float4(hsum(aI), hsum(aF), hsum(aG), hsum(aO));
                }
            }
        } else {
            // ---- L2 + head: steps [(w-2)*KW, (w-2)*KW+KW) ----
            #pragma unroll
            for (int k = 0; k < KW; ++k) {
                const int t1 = (w - 2) * KW + k;
                if (t1 >= i2 && t1 < span) {
                    const int pp = t1 & 1;
                    float4 pv = pr[t1 & (RING - 1)][u];
                    ull aI = pack2(pv.x, 0.f), aF = pack2(pv.y, 0.f);
                    ull aG = pack2(pv.z, 0.f), aO = pack2(pv.w, 0.f);
                    const ulonglong2* hb = (const ulonglong2*)h1buf[pp ^ 1];
                    DOT20(wI, wF, wG, wO, hb, aI, aF, aG, aO);
                    lstm_act4(aI, aF, aG, aO, cst, h);
                    h1buf[pp][u] = h;
                    if (t1 >= ihl) {
                        float part = h * wlin_u;           // zero on idle lanes
                        part += __shfl_xor_sync(0xFFFFFFFFu, part, 16);
                        part += __shfl_xor_sync(0xFFFFFFFFu, part, 8);
                        part += __shfl_xor_sync(0xFFFFFFFFu, part, 4);
                        part += __shfl_xor_sync(0xFFFFFFFFu, part, 2);
                        part += __shfl_xor_sync(0xFFFFFFFFu, part, 1);
                        if (lane == 0) out[s1 + t1] = fmaf(part, 0.01f, blinsc);
                    }
                }
                __syncwarp();
            }
        }
        __syncthreads();
    }

    // final states: [update(N), h0(20), h1(20), c0(20), c1(20)]
    if (end_out == N && out_size >= N + 80 && act) {
        if (wid == 0)      { out[N + u]      = h; out[N + 40 + u] = cst; }
        else if (wid == 1) { out[N + 20 + u] = h; out[N + 60 + u] = cst; }
    }
}

extern "C" void kernel_launch(void* const* d_in, const int* in_sizes, int n_in,
                              void* d_out, int out_size) {
    const float* grad = (const float*)d_in[0];
    const float* Wih0 = (const float*)d_in[1];
    const float* Whh0 = (const float*)d_in[2];
    const float* bih0 = (const float*)d_in[3];
    const float* bhh0 = (const float*)d_in[4];
    const float* Wih1 = (const float*)d_in[5];
    const float* Whh1 = (const float*)d_in[6];
    const float* bih1 = (const float*)d_in[7];
    const float* bhh1 = (const float*)d_in[8];
    const float* Wlin = (const float*)d_in[9];
    const float* blin = (const float*)d_in[10];

    int N = in_sizes[0];
    // 740 chunk slots = 5 blocks/SM x 148 SMs, one wave
    int chl = (N + 739) / 740;
    if (chl > XB - 2 * CH_W) chl = XB - 2 * CH_W;
    if (chl < 1) chl = 1;
    int grid = (N + chl - 1) / chl;
    lstm_opt_kernel<<<grid, TPB>>>(grad, Wih0, Whh0, bih0, bhh0,
                                   Wih1, Whh1, bih1, bhh1, Wlin, blin,
                                   (float*)d_out, N, out_size, chl);
}